// round 4
// baseline (speedup 1.0000x reference)
#include <cuda_runtime.h>
#include <cstdint>

#define B_  4
#define C_  64
#define N_  4096
#define IC_ 32
#define N1_ (N_ + 1)

// ---------------- device scratch (no allocations allowed) ----------------
__device__ float  d_wA[C_], d_wP[C_];
__device__ float  d_cA, d_cP;
__device__ float  d_g[B_ * N_ * C_];        // g_x, layout [b][n][o]
__device__ float  d_a[B_ * N_];
__device__ float  d_p[B_ * N_];
__device__ float  d_q[B_ * N_];             // sorted p per batch (ascending)
__device__ int    d_perm[B_ * N_];
__device__ double d_part1[B_ * 64 * 64];    // per-chunk partials [b][ch][o]
__device__ double d_part2[B_ * 64 * 64];
__device__ double d_off1[B_ * 64 * 64];     // suffix-exclusive chunk offsets
__device__ double d_off2[B_ * 64 * 64];     // prefix-exclusive chunk offsets
__device__ float  d_S1[B_ * N1_ * C_];      // suffix-inclusive sums [b][k][o]
__device__ float  d_S2[B_ * N1_ * C_];      // prefix-exclusive sums
__device__ float  d_T1[B_ * N1_];
__device__ float  d_T2[B_ * N1_];
__device__ int    d_flag;

// ---------------- kernel 0: fold cp_w into theta/phi weights ----------------
__global__ void k_prep(const float* __restrict__ tw, const float* __restrict__ tb,
                       const float* __restrict__ pw, const float* __restrict__ pb,
                       const float* __restrict__ cp) {
    int c = threadIdx.x;   // 64 threads
    float wa = 0.f, wp = 0.f;
    for (int i = 0; i < IC_; ++i) {
        wa += cp[i]       * tw[i * C_ + c];
        wp += cp[IC_ + i] * pw[i * C_ + c];
    }
    d_wA[c] = wa;
    d_wP[c] = wp;
    if (c == 0) {
        float ca = 0.f, cpv = 0.f;
        for (int i = 0; i < IC_; ++i) { ca += cp[i] * tb[i]; cpv += cp[IC_ + i] * pb[i]; }
        d_cA = ca; d_cP = cpv;
    }
}

// ---------------- kernel 1: g_x GEMM + a,p projections ----------------
// grid (32, B), block 128. Each thread handles one node n.
__global__ void k_gxap(const float* __restrict__ x, const float* __restrict__ gw,
                       const float* __restrict__ gb) {
    __shared__ float sgwT[C_ * C_];   // transposed: [c][o]
    __shared__ float sgb[C_], swA[C_], swP[C_];
    int tid = threadIdx.x;
    int b = blockIdx.y;
    int n = blockIdx.x * 128 + tid;

    for (int idx = tid; idx < C_ * C_; idx += 128) {
        int c = idx >> 6, o = idx & 63;
        sgwT[idx] = gw[o * C_ + c];
    }
    if (tid < C_) { sgb[tid] = gb[tid]; swA[tid] = d_wA[tid]; swP[tid] = d_wP[tid]; }
    __syncthreads();

    float acc[C_];
#pragma unroll
    for (int o = 0; o < C_; ++o) acc[o] = 0.f;
    float aa = d_cA, pp = d_cP;

    for (int c = 0; c < C_; ++c) {
        float xc = x[((size_t)b * C_ + c) * N_ + n];
        aa += swA[c] * xc;
        pp += swP[c] * xc;
        const float4* row = (const float4*)&sgwT[c * C_];
#pragma unroll
        for (int o4 = 0; o4 < 16; ++o4) {
            float4 w = row[o4];
            acc[o4 * 4 + 0] += xc * w.x;
            acc[o4 * 4 + 1] += xc * w.y;
            acc[o4 * 4 + 2] += xc * w.z;
            acc[o4 * 4 + 3] += xc * w.w;
        }
    }
    d_a[b * N_ + n] = aa;
    d_p[b * N_ + n] = pp;

    float4* gout = (float4*)&d_g[((size_t)b * N_ + n) * C_];
#pragma unroll
    for (int o4 = 0; o4 < 16; ++o4) {
        float4 v;
        v.x = acc[o4 * 4 + 0] + sgb[o4 * 4 + 0];
        v.y = acc[o4 * 4 + 1] + sgb[o4 * 4 + 1];
        v.z = acc[o4 * 4 + 2] + sgb[o4 * 4 + 2];
        v.w = acc[o4 * 4 + 3] + sgb[o4 * 4 + 3];
        gout[o4] = v;
    }
}

// ---------------- kernel 2: per-batch bitonic sort of p ----------------
__global__ void k_sort() {
    __shared__ float sv[N_];
    __shared__ int   si[N_];
    int b = blockIdx.x;
    for (int t = threadIdx.x; t < N_; t += 1024) { sv[t] = d_p[b * N_ + t]; si[t] = t; }
    __syncthreads();
    for (int k = 2; k <= N_; k <<= 1) {
        for (int j = k >> 1; j > 0; j >>= 1) {
            for (int t = threadIdx.x; t < N_; t += 1024) {
                int ixj = t ^ j;
                if (ixj > t) {
                    bool up = ((t & k) == 0);
                    float va = sv[t], vb = sv[ixj];
                    if ((va > vb) == up) {
                        sv[t] = vb; sv[ixj] = va;
                        int ia = si[t]; si[t] = si[ixj]; si[ixj] = ia;
                    }
                }
            }
            __syncthreads();
        }
    }
    for (int t = threadIdx.x; t < N_; t += 1024) {
        d_q[b * N_ + t] = sv[t];
        d_perm[b * N_ + t] = si[t];
    }
}

// term values for sorted index k, channel o
__device__ __forceinline__ void term_vals(int b, int k, int o, float& t1, float& t2) {
    float qv = d_q[b * N_ + k];
    int pj = d_perm[b * N_ + k];
    float gv = d_g[((size_t)b * N_ + pj) * C_ + o];
    t1 = expf(qv) * gv;
    t2 = expf(0.2f * qv) * gv;
}

// ---------------- kernel 3: per-chunk partial sums ----------------
// grid (64 chunks, B), block 512: o = tid&63, r = tid>>6, 8 k per thread
__global__ void k_scanA() {
    __shared__ double sh1[512], sh2[512];
    int tid = threadIdx.x;
    int b = blockIdx.y, ch = blockIdx.x;
    int o = tid & 63, r = tid >> 6;
    int k0 = ch * 64 + r * 8;
    double s1 = 0.0, s2 = 0.0;
    for (int u = 0; u < 8; ++u) {
        float t1, t2; term_vals(b, k0 + u, o, t1, t2);
        s1 += (double)t1; s2 += (double)t2;
    }
    sh1[tid] = s1; sh2[tid] = s2;
    __syncthreads();
    if (r == 0) {
        double a1 = 0.0, a2 = 0.0;
        for (int rr = 0; rr < 8; ++rr) { a1 += sh1[rr * 64 + o]; a2 += sh2[rr * 64 + o]; }
        d_part1[(b * 64 + ch) * 64 + o] = a1;
        d_part2[(b * 64 + ch) * 64 + o] = a2;
    }
}

// ---------------- kernel 4: scan chunk partials -> offsets + boundaries ----------------
// grid B, block 64 (one thread per channel)
__global__ void k_scanB() {
    int b = blockIdx.x, o = threadIdx.x;
    double run2 = 0.0;
    for (int ch = 0; ch < 64; ++ch) {
        d_off2[(b * 64 + ch) * 64 + o] = run2;
        run2 += d_part2[(b * 64 + ch) * 64 + o];
    }
    double run1 = 0.0;
    for (int ch = 63; ch >= 0; --ch) {
        d_off1[(b * 64 + ch) * 64 + o] = run1;
        run1 += d_part1[(b * 64 + ch) * 64 + o];
    }
    d_S1[((size_t)b * N1_ + N_) * C_ + o] = 0.f;
    d_S2[((size_t)b * N1_ + N_) * C_ + o] = (float)run2;
}

// ---------------- kernel 5: scalar T scans (partition function pieces) ----------------
// grid B, block 1024, 4 elements per thread, double Hillis-Steele
__global__ void k_tscan() {
    __shared__ double sh[1024];
    __shared__ double totsh;
    int b = blockIdx.x, tid = threadIdx.x;
    int k0 = tid * 4;
    float e1[4], e2[4];
    for (int u = 0; u < 4; ++u) {
        float qv = d_q[b * N_ + k0 + u];
        e1[u] = expf(qv);
        e2[u] = expf(0.2f * qv);
    }
    // scan 1 (ep1) -> T1 suffix-inclusive = total - prefix_exclusive
    double ts = 0.0; for (int u = 0; u < 4; ++u) ts += e1[u];
    sh[tid] = ts; __syncthreads();
    for (int off = 1; off < 1024; off <<= 1) {
        double add = (tid >= off) ? sh[tid - off] : 0.0;
        __syncthreads();
        sh[tid] += add;
        __syncthreads();
    }
    double base1 = sh[tid] - ts;
    if (tid == 1023) totsh = sh[1023];
    __syncthreads();
    double tot1 = totsh;
    double pe = base1;
    for (int u = 0; u < 4; ++u) { d_T1[(size_t)b * N1_ + k0 + u] = (float)(tot1 - pe); pe += e1[u]; }
    __syncthreads();
    // scan 2 (ep2) -> T2 prefix-exclusive
    ts = 0.0; for (int u = 0; u < 4; ++u) ts += e2[u];
    sh[tid] = ts; __syncthreads();
    for (int off = 1; off < 1024; off <<= 1) {
        double add = (tid >= off) ? sh[tid - off] : 0.0;
        __syncthreads();
        sh[tid] += add;
        __syncthreads();
    }
    double base2 = sh[tid] - ts;
    if (tid == 1023) totsh = sh[1023];
    __syncthreads();
    double run = base2;
    for (int u = 0; u < 4; ++u) { d_T2[(size_t)b * N1_ + k0 + u] = (float)run; run += e2[u]; }
    if (tid == 0) {
        d_T1[(size_t)b * N1_ + N_] = 0.f;
        d_T2[(size_t)b * N1_ + N_] = (float)totsh;
    }
}

// ---------------- kernel 6: write full S1/S2 arrays ----------------
__global__ void k_scanC() {
    __shared__ double sh1[512], sh2[512];
    int tid = threadIdx.x;
    int b = blockIdx.y, ch = blockIdx.x;
    int o = tid & 63, r = tid >> 6;
    int k0 = ch * 64 + r * 8;
    float v1[8], v2[8];
    double t1 = 0.0, t2 = 0.0;
    for (int u = 0; u < 8; ++u) {
        term_vals(b, k0 + u, o, v1[u], v2[u]);
        t1 += (double)v1[u]; t2 += (double)v2[u];
    }
    sh1[tid] = t1; sh2[tid] = t2;
    __syncthreads();
    double base1 = d_off1[(b * 64 + ch) * 64 + o];
    for (int rr = r + 1; rr < 8; ++rr) base1 += sh1[rr * 64 + o];
    double base2 = d_off2[(b * 64 + ch) * 64 + o];
    for (int rr = 0; rr < r; ++rr) base2 += sh2[rr * 64 + o];

    double s = base1;                              // suffix-inclusive
    for (int u = 7; u >= 0; --u) {
        s += (double)v1[u];
        d_S1[((size_t)b * N1_ + (k0 + u)) * C_ + o] = (float)s;
    }
    double sp = base2;                             // prefix-exclusive
    for (int u = 0; u < 8; ++u) {
        d_S2[((size_t)b * N1_ + (k0 + u)) * C_ + o] = (float)sp;
        sp += (double)v2[u];
    }
}

// ---------------- kernel 7: final attention output ----------------
// grid (32, B), block 128: one node i per thread, staged transpose for coalesced store
__global__ void k_final(float* __restrict__ out) {
    __shared__ float sout[C_ * 128];
    int tid = threadIdx.x;
    int b = blockIdx.y;
    int i0 = blockIdx.x * 128;
    int i = i0 + tid;

    float aa = d_a[b * N_ + i];
    float tgt = -aa;
    const float* qb = &d_q[b * N_];
    int lo = 0, cnt = N_;
    while (cnt > 0) {                       // first k with q[k] >= -a_i
        int st = cnt >> 1;
        int mid = lo + st;
        if (qb[mid] < tgt) { lo = mid + 1; cnt -= st + 1; }
        else cnt = st;
    }
    int k = lo;
    float e1 = expf(aa), e2 = expf(0.2f * aa);
    float Z = e1 * d_T1[(size_t)b * N1_ + k] + e2 * d_T2[(size_t)b * N1_ + k];
    float w1 = e1 / Z, w2 = e2 / Z;

    const float4* s1p = (const float4*)&d_S1[((size_t)b * N1_ + k) * C_];
    const float4* s2p = (const float4*)&d_S2[((size_t)b * N1_ + k) * C_];
#pragma unroll
    for (int o4 = 0; o4 < 16; ++o4) {
        float4 A = s1p[o4], Bv = s2p[o4];
        sout[(o4 * 4 + 0) * 128 + tid] = w1 * A.x + w2 * Bv.x;
        sout[(o4 * 4 + 1) * 128 + tid] = w1 * A.y + w2 * Bv.y;
        sout[(o4 * 4 + 2) * 128 + tid] = w1 * A.z + w2 * Bv.z;
        sout[(o4 * 4 + 3) * 128 + tid] = w1 * A.w + w2 * Bv.w;
    }
    __syncthreads();
    float* outp = out + (size_t)b * C_ * N_;
    for (int idx = tid; idx < C_ * 128; idx += 128) {
        int o = idx >> 7, il = idx & 127;
        outp[(size_t)o * N_ + i0 + il] = sout[idx];
    }
}

// ---------------- C_k handling ----------------
__global__ void k_flag_reset() { d_flag = 0; }

__global__ void k_flag_scan(const float* __restrict__ Ck) {
    const float4* f4 = (const float4*)Ck;
    const int total4 = (N_ * N_) / 4;            // 4,194,304
    int gid = blockIdx.x * blockDim.x + threadIdx.x;
    for (int v = gid; v < total4; v += gridDim.x * blockDim.x) {
        float4 c = f4[v];
        if (c.x != 0.f || c.y != 0.f || c.z != 0.f || c.w != 0.f) d_flag = 1;
    }
}

// cold path: y += C_k @ g_x  (only runs when C_k has any nonzero)
__global__ void k_ckgemm(const float* __restrict__ Ck, float* __restrict__ out) {
    if (!d_flag) return;
    __shared__ float Ash[64][65];
    __shared__ float Bsh[64][64];
    int t = threadIdx.x;          // 256
    int b = blockIdx.y;
    int i0 = blockIdx.x * 64;
    int ti = t >> 4, to = t & 15;
    float acc[4][4];
#pragma unroll
    for (int a = 0; a < 4; ++a)
#pragma unroll
        for (int c = 0; c < 4; ++c) acc[a][c] = 0.f;

    for (int j0 = 0; j0 < N_; j0 += 64) {
        for (int idx = t; idx < 4096; idx += 256) {
            int ii = idx >> 6, jj = idx & 63;
            Ash[ii][jj] = Ck[(size_t)(i0 + ii) * N_ + j0 + jj];
        }
        for (int idx = t; idx < 4096; idx += 256) {
            int jj = idx >> 6, o = idx & 63;
            Bsh[jj][o] = d_g[((size_t)b * N_ + j0 + jj) * C_ + o];
        }
        __syncthreads();
        for (int jj = 0; jj < 64; ++jj) {
            float a0 = Ash[ti * 4 + 0][jj], a1 = Ash[ti * 4 + 1][jj];
            float a2 = Ash[ti * 4 + 2][jj], a3 = Ash[ti * 4 + 3][jj];
            float b0 = Bsh[jj][to * 4 + 0], b1 = Bsh[jj][to * 4 + 1];
            float b2 = Bsh[jj][to * 4 + 2], b3 = Bsh[jj][to * 4 + 3];
            acc[0][0] += a0 * b0; acc[0][1] += a0 * b1; acc[0][2] += a0 * b2; acc[0][3] += a0 * b3;
            acc[1][0] += a1 * b0; acc[1][1] += a1 * b1; acc[1][2] += a1 * b2; acc[1][3] += a1 * b3;
            acc[2][0] += a2 * b0; acc[2][1] += a2 * b1; acc[2][2] += a2 * b2; acc[2][3] += a2 * b3;
            acc[3][0] += a3 * b0; acc[3][1] += a3 * b1; acc[3][2] += a3 * b2; acc[3][3] += a3 * b3;
        }
        __syncthreads();
    }
#pragma unroll
    for (int ii = 0; ii < 4; ++ii)
#pragma unroll
        for (int oo = 0; oo < 4; ++oo)
            out[((size_t)b * C_ + to * 4 + oo) * N_ + i0 + ti * 4 + ii] += acc[ii][oo];
}

// ---------------- launch ----------------
extern "C" void kernel_launch(void* const* d_in, const int* in_sizes, int n_in,
                              void* d_out, int out_size) {
    const float* x   = (const float*)d_in[0];
    const float* gw  = (const float*)d_in[1];
    const float* gb  = (const float*)d_in[2];
    const float* tw  = (const float*)d_in[3];
    const float* tb  = (const float*)d_in[4];
    const float* pw  = (const float*)d_in[5];
    const float* pb  = (const float*)d_in[6];
    const float* cp  = (const float*)d_in[7];
    const float* Ck  = (const float*)d_in[8];
    float* out = (float*)d_out;

    k_flag_reset<<<1, 1>>>();
    k_flag_scan<<<4096, 256>>>(Ck);
    k_prep<<<1, 64>>>(tw, tb, pw, pb, cp);
    k_gxap<<<dim3(32, B_), 128>>>(x, gw, gb);
    k_sort<<<B_, 1024>>>();
    k_scanA<<<dim3(64, B_), 512>>>();
    k_scanB<<<B_, 64>>>();
    k_tscan<<<B_, 1024>>>();
    k_scanC<<<dim3(64, B_), 512>>>();
    k_final<<<dim3(32, B_), 128>>>(out);
    k_ckgemm<<<dim3(64, B_), 256>>>(Ck, out);
}

// round 6
// speedup vs baseline: 1.5431x; 1.5431x over previous
#include <cuda_runtime.h>
#include <cstdint>

#define B_  4
#define C_  64
#define N_  4096
#define IC_ 32
#define N1_ (N_ + 1)

// ---------------- device scratch (no allocations allowed) ----------------
__device__ float  d_wA[C_], d_wP[C_];
__device__ float  d_cA, d_cP;
__device__ float  d_g[B_ * N_ * C_];        // g_x, layout [b][n][o]
__device__ float  d_a[B_ * N_];
__device__ float  d_p[B_ * N_];
__device__ float  d_qa[B_ * N_];            // chunk-sorted (runs of 1024)
__device__ int    d_pa[B_ * N_];
__device__ float  d_qb[B_ * N_];            // runs of 2048
__device__ int    d_pb[B_ * N_];
__device__ float  d_q[B_ * N_];             // fully sorted ascending
__device__ int    d_perm[B_ * N_];
__device__ float  d_e1[B_ * N_];            // exp(q)
__device__ float  d_e2[B_ * N_];            // exp(0.2q)
__device__ double d_part1[B_ * 64 * 64];    // per-chunk partials [b][ch][o]
__device__ double d_part2[B_ * 64 * 64];
__device__ double d_off1[B_ * 64 * 64];     // suffix-exclusive chunk offsets
__device__ double d_off2[B_ * 64 * 64];     // prefix-exclusive chunk offsets
__device__ float  d_S1[B_ * N1_ * C_];      // suffix-inclusive sums [b][k][o]
__device__ float  d_S2[B_ * N1_ * C_];      // prefix-exclusive sums
__device__ float  d_T1[B_ * N1_];
__device__ float  d_T2[B_ * N1_];
__device__ int    d_flag;

// ---------------- kernel 0: fold cp_w into theta/phi weights + flag reset ----
__global__ void k_prep(const float* __restrict__ tw, const float* __restrict__ tb,
                       const float* __restrict__ pw, const float* __restrict__ pb,
                       const float* __restrict__ cp) {
    int c = threadIdx.x;   // 64 threads
    float wa = 0.f, wp = 0.f;
    for (int i = 0; i < IC_; ++i) {
        wa += cp[i]       * tw[i * C_ + c];
        wp += cp[IC_ + i] * pw[i * C_ + c];
    }
    d_wA[c] = wa;
    d_wP[c] = wp;
    if (c == 0) {
        float ca = 0.f, cpv = 0.f;
        for (int i = 0; i < IC_; ++i) { ca += cp[i] * tb[i]; cpv += cp[IC_ + i] * pb[i]; }
        d_cA = ca; d_cP = cpv;
        d_flag = 0;
    }
}

// ---------------- kernel 1: g_x GEMM + a,p projections (register tiled) ----
// grid (32, B), block 256. Tile: 128 nodes x 64 channels.
// Thread layout: tx = tid%16 (channel quad o = tx*4..+3), ty = tid/16 (nodes ty*8..+7).
// K=64 split into two 32-deep halves to keep static smem under 48KB.
__global__ void k_gxap(const float* __restrict__ x, const float* __restrict__ gw,
                       const float* __restrict__ gb) {
    __shared__ float sx[32 * 128];        // [cc][n]  (one K-half)
    __shared__ float sw[64 * 68];         // [c][o] padded row 68 (float4-aligned)
    __shared__ float swA[C_], swP[C_], sgb[C_];
    int tid = threadIdx.x;
    int b = blockIdx.y;
    int n0 = blockIdx.x * 128;
    int tx = tid & 15, ty = tid >> 4;

    // load transposed weights (coalesced gmem read; padded smem rows)
    for (int idx = tid; idx < C_ * C_; idx += 256) {
        int o = idx >> 6, c = idx & 63;
        sw[c * 68 + o] = gw[o * C_ + c];
    }
    if (tid < C_) { swA[tid] = d_wA[tid]; swP[tid] = d_wP[tid]; sgb[tid] = gb[tid]; }

    float acc[8][4];
#pragma unroll
    for (int nn = 0; nn < 8; ++nn)
#pragma unroll
        for (int j = 0; j < 4; ++j) acc[nn][j] = 0.f;
    float aa = d_cA, pp = d_cP;

    for (int h = 0; h < 2; ++h) {
        __syncthreads();
        // load x half: c = h*32+cc, coalesced float4 along n
        const float4* x4 = (const float4*)x;
        float4* sx4 = (float4*)sx;
        for (int idx = tid; idx < 32 * 32; idx += 256) {   // 32 c rows x 32 float4
            int cc = idx >> 5, n4 = idx & 31;
            sx4[cc * 32 + n4] = x4[((size_t)(b * C_ + h * 32 + cc) * N_ + n0) / 4 + n4];
        }
        __syncthreads();
#pragma unroll 4
        for (int cc = 0; cc < 32; ++cc) {
            int c = h * 32 + cc;
            float4 wv = *(const float4*)&sw[c * 68 + tx * 4];
#pragma unroll
            for (int nn = 0; nn < 8; ++nn) {
                float xv = sx[cc * 128 + ty * 8 + nn];
                acc[nn][0] += xv * wv.x;
                acc[nn][1] += xv * wv.y;
                acc[nn][2] += xv * wv.z;
                acc[nn][3] += xv * wv.w;
            }
        }
        // a,p projections: threads 0..127, one node each
        if (tid < 128) {
            for (int cc = 0; cc < 32; ++cc) {
                float xv = sx[cc * 128 + tid];
                aa += swA[h * 32 + cc] * xv;
                pp += swP[h * 32 + cc] * xv;
            }
        }
    }
    __syncthreads();
    if (tid < 128) {
        d_a[b * N_ + n0 + tid] = aa;
        d_p[b * N_ + n0 + tid] = pp;
    }
    float4 bias = *(const float4*)&sgb[tx * 4];
#pragma unroll
    for (int nn = 0; nn < 8; ++nn) {
        float4 v;
        v.x = acc[nn][0] + bias.x;
        v.y = acc[nn][1] + bias.y;
        v.z = acc[nn][2] + bias.z;
        v.w = acc[nn][3] + bias.w;
        *(float4*)&d_g[((size_t)(b * N_ + n0 + ty * 8 + nn)) * C_ + tx * 4] = v;
    }
}

// ---------------- kernel 2a: chunk bitonic sort (1024 elems per block) -------
__global__ void k_csort() {
    __shared__ float sv[1024];
    __shared__ int   si[1024];
    int b = blockIdx.y, ch = blockIdx.x;          // 4 chunks per batch
    int base = ch * 1024;
    for (int t = threadIdx.x; t < 1024; t += 512) {
        sv[t] = d_p[b * N_ + base + t];
        si[t] = base + t;
    }
    __syncthreads();
    for (int k = 2; k <= 1024; k <<= 1) {
        for (int j = k >> 1; j > 0; j >>= 1) {
            for (int t = threadIdx.x; t < 1024; t += 512) {
                int ixj = t ^ j;
                if (ixj > t) {
                    bool up = ((t & k) == 0);
                    float va = sv[t], vb = sv[ixj];
                    if ((va > vb) == up) {
                        sv[t] = vb; sv[ixj] = va;
                        int ia = si[t]; si[t] = si[ixj]; si[ixj] = ia;
                    }
                }
            }
            __syncthreads();
        }
    }
    for (int t = threadIdx.x; t < 1024; t += 512) {
        d_qa[b * N_ + base + t] = sv[t];
        d_pa[b * N_ + base + t] = si[t];
    }
}

// ---------------- kernel 2b: merge-path merge of adjacent runs ---------------
// Pointers to the device-global buffers are bound IN DEVICE CODE (host code must
// never pass a __device__ symbol as a kernel argument — that passes the host
// shadow address and reads garbage).
// grid (16, B), block 256: each thread produces one merged output element.
template <int RUNLEN>
__global__ void k_merge() {
    const float* qin;  const int* pin;  float* qout;  int* pout;
    if (RUNLEN == 1024) { qin = d_qa; pin = d_pa; qout = d_qb; pout = d_pb; }
    else                { qin = d_qb; pin = d_pb; qout = d_q;  pout = d_perm; }
    const int runLen = RUNLEN;
    int b = blockIdx.y;
    int t = blockIdx.x * 256 + threadIdx.x;       // 0..N_-1
    int pairLen = runLen * 2;
    int pair = t / pairLen;
    int d = t - pair * pairLen;
    const float* A  = qin + (size_t)b * N_ + pair * pairLen;
    const float* Bq = A + runLen;
    const int*   Ai = pin + (size_t)b * N_ + pair * pairLen;
    const int*   Bi = Ai + runLen;
    int lo = d - runLen; if (lo < 0) lo = 0;
    int hi = d < runLen ? d : runLen;
    while (lo < hi) {                              // rank of split in A (stable, A-first)
        int mid = (lo + hi) >> 1;
        if (A[mid] <= Bq[d - 1 - mid]) lo = mid + 1; else hi = mid;
    }
    int i = lo, j = d - lo;
    bool takeA = (i < runLen) && (j >= runLen || A[i] <= Bq[j]);
    qout[(size_t)b * N_ + pair * pairLen + d] = takeA ? A[i] : Bq[j];
    pout[(size_t)b * N_ + pair * pairLen + d] = takeA ? Ai[i] : Bi[j];
}

// ---------------- kernel 3: exp cache + scalar T scans (warp-shuffle) --------
// grid B, block 512, 8 elements/thread.
__global__ void k_tscan() {
    __shared__ double ws1[16], ws2[16], tots[2];
    int b = blockIdx.x, tid = threadIdx.x;
    int lane = tid & 31, w = tid >> 5;
    int k0 = tid * 8;
    float e1v[8], e2v[8];
    double s1 = 0.0, s2 = 0.0;
#pragma unroll
    for (int u = 0; u < 8; ++u) {
        float qv = d_q[b * N_ + k0 + u];
        e1v[u] = expf(qv);
        e2v[u] = expf(0.2f * qv);
        d_e1[b * N_ + k0 + u] = e1v[u];
        d_e2[b * N_ + k0 + u] = e2v[u];
        s1 += (double)e1v[u]; s2 += (double)e2v[u];
    }
    double i1 = s1, i2 = s2;
#pragma unroll
    for (int off = 1; off < 32; off <<= 1) {
        double t1 = __shfl_up_sync(0xffffffffu, i1, off);
        double t2 = __shfl_up_sync(0xffffffffu, i2, off);
        if (lane >= off) { i1 += t1; i2 += t2; }
    }
    if (lane == 31) { ws1[w] = i1; ws2[w] = i2; }
    __syncthreads();
    if (tid == 0) {
        double r1 = 0.0, r2 = 0.0;
        for (int ww = 0; ww < 16; ++ww) {
            double t1 = ws1[ww], t2 = ws2[ww];
            ws1[ww] = r1; ws2[ww] = r2;
            r1 += t1; r2 += t2;
        }
        tots[0] = r1; tots[1] = r2;
    }
    __syncthreads();
    double base1 = ws1[w] + (i1 - s1);
    double base2 = ws2[w] + (i2 - s2);
    double tot1 = tots[0], tot2 = tots[1];
    double pe = base1;
#pragma unroll
    for (int u = 0; u < 8; ++u) { d_T1[(size_t)b * N1_ + k0 + u] = (float)(tot1 - pe); pe += (double)e1v[u]; }
    pe = base2;
#pragma unroll
    for (int u = 0; u < 8; ++u) { d_T2[(size_t)b * N1_ + k0 + u] = (float)pe; pe += (double)e2v[u]; }
    if (tid == 0) {
        d_T1[(size_t)b * N1_ + N_] = 0.f;
        d_T2[(size_t)b * N1_ + N_] = (float)tot2;
    }
}

// term values for sorted index k, channel o (uses cached exps)
__device__ __forceinline__ void term_vals(int b, int k, int o, float& t1, float& t2) {
    int pj = d_perm[b * N_ + k];
    float gv = d_g[((size_t)b * N_ + pj) * C_ + o];
    t1 = d_e1[b * N_ + k] * gv;
    t2 = d_e2[b * N_ + k] * gv;
}

// ---------------- kernel 4: per-chunk partial sums ---------------------------
// grid (64 chunks, B), block 512: o = tid&63, r = tid>>6, 8 k per thread
__global__ void k_scanA() {
    __shared__ double sh1[512], sh2[512];
    int tid = threadIdx.x;
    int b = blockIdx.y, ch = blockIdx.x;
    int o = tid & 63, r = tid >> 6;
    int k0 = ch * 64 + r * 8;
    double s1 = 0.0, s2 = 0.0;
#pragma unroll
    for (int u = 0; u < 8; ++u) {
        float t1, t2; term_vals(b, k0 + u, o, t1, t2);
        s1 += (double)t1; s2 += (double)t2;
    }
    sh1[tid] = s1; sh2[tid] = s2;
    __syncthreads();
    if (r == 0) {
        double a1 = 0.0, a2 = 0.0;
        for (int rr = 0; rr < 8; ++rr) { a1 += sh1[rr * 64 + o]; a2 += sh2[rr * 64 + o]; }
        d_part1[(b * 64 + ch) * 64 + o] = a1;
        d_part2[(b * 64 + ch) * 64 + o] = a2;
    }
}

// ---------------- kernel 5: chunk-offset scans, one warp per (b,o) -----------
// grid 8, block 1024 (32 warps): global warp id = (b,o).
__global__ void k_scanB() {
    int gwid = blockIdx.x * 32 + (threadIdx.x >> 5);
    int lane = threadIdx.x & 31;
    int b = gwid >> 6, o = gwid & 63;

    // prefix scan of part2 over 64 chunks (2 per lane, ascending)
    double v0 = d_part2[(b * 64 + 2 * lane) * 64 + o];
    double v1 = d_part2[(b * 64 + 2 * lane + 1) * 64 + o];
    double s = v0 + v1, inc = s;
#pragma unroll
    for (int off = 1; off < 32; off <<= 1) {
        double t = __shfl_up_sync(0xffffffffu, inc, off);
        if (lane >= off) inc += t;
    }
    double excl = inc - s;
    d_off2[(b * 64 + 2 * lane) * 64 + o] = excl;
    d_off2[(b * 64 + 2 * lane + 1) * 64 + o] = excl + v0;
    double tot2 = __shfl_sync(0xffffffffu, inc, 31);

    // suffix scan of part1 (2 per lane, descending)
    double u0 = d_part1[(b * 64 + (63 - 2 * lane)) * 64 + o];
    double u1 = d_part1[(b * 64 + (62 - 2 * lane)) * 64 + o];
    double su = u0 + u1, incu = su;
#pragma unroll
    for (int off = 1; off < 32; off <<= 1) {
        double t = __shfl_up_sync(0xffffffffu, incu, off);
        if (lane >= off) incu += t;
    }
    double exclu = incu - su;
    d_off1[(b * 64 + (63 - 2 * lane)) * 64 + o] = exclu;
    d_off1[(b * 64 + (62 - 2 * lane)) * 64 + o] = exclu + u0;

    if (lane == 0) {
        d_S1[((size_t)b * N1_ + N_) * C_ + o] = 0.f;
        d_S2[((size_t)b * N1_ + N_) * C_ + o] = (float)tot2;
    }
}

// ---------------- kernel 6: write full S1/S2 arrays --------------------------
__global__ void k_scanC() {
    __shared__ double sh1[512], sh2[512];
    int tid = threadIdx.x;
    int b = blockIdx.y, ch = blockIdx.x;
    int o = tid & 63, r = tid >> 6;
    int k0 = ch * 64 + r * 8;
    float v1[8], v2[8];
    double t1 = 0.0, t2 = 0.0;
#pragma unroll
    for (int u = 0; u < 8; ++u) {
        term_vals(b, k0 + u, o, v1[u], v2[u]);
        t1 += (double)v1[u]; t2 += (double)v2[u];
    }
    sh1[tid] = t1; sh2[tid] = t2;
    __syncthreads();
    double base1 = d_off1[(b * 64 + ch) * 64 + o];
    for (int rr = r + 1; rr < 8; ++rr) base1 += sh1[rr * 64 + o];
    double base2 = d_off2[(b * 64 + ch) * 64 + o];
    for (int rr = 0; rr < r; ++rr) base2 += sh2[rr * 64 + o];

    double s = base1;                              // suffix-inclusive
#pragma unroll
    for (int u = 7; u >= 0; --u) {
        s += (double)v1[u];
        d_S1[((size_t)b * N1_ + (k0 + u)) * C_ + o] = (float)s;
    }
    double sp = base2;                             // prefix-exclusive
#pragma unroll
    for (int u = 0; u < 8; ++u) {
        d_S2[((size_t)b * N1_ + (k0 + u)) * C_ + o] = (float)sp;
        sp += (double)v2[u];
    }
}

// ---------------- kernel 7: final attention output ---------------------------
// grid (32, B), block 128: one node i per thread, smem-staged q + transpose
__global__ void k_final(float* __restrict__ out) {
    __shared__ float sq[N_];                 // 16KB
    __shared__ float sout[C_ * 128];         // 32KB
    int tid = threadIdx.x;
    int b = blockIdx.y;
    int i0 = blockIdx.x * 128;

    for (int t = tid; t < N_; t += 128) sq[t] = d_q[b * N_ + t];
    __syncthreads();

    float aa = d_a[b * N_ + i0 + tid];
    float tgt = -aa;
    int lo = 0, cnt = N_;
    while (cnt > 0) {                        // first k with q[k] >= -a_i
        int st = cnt >> 1;
        int mid = lo + st;
        if (sq[mid] < tgt) { lo = mid + 1; cnt -= st + 1; }
        else cnt = st;
    }
    int k = lo;
    float e1 = expf(aa), e2 = expf(0.2f * aa);
    float Z = e1 * d_T1[(size_t)b * N1_ + k] + e2 * d_T2[(size_t)b * N1_ + k];
    float w1 = e1 / Z, w2 = e2 / Z;

    const float4* s1p = (const float4*)&d_S1[((size_t)b * N1_ + k) * C_];
    const float4* s2p = (const float4*)&d_S2[((size_t)b * N1_ + k) * C_];
#pragma unroll
    for (int o4 = 0; o4 < 16; ++o4) {
        float4 A = s1p[o4], Bv = s2p[o4];
        sout[(o4 * 4 + 0) * 128 + tid] = w1 * A.x + w2 * Bv.x;
        sout[(o4 * 4 + 1) * 128 + tid] = w1 * A.y + w2 * Bv.y;
        sout[(o4 * 4 + 2) * 128 + tid] = w1 * A.z + w2 * Bv.z;
        sout[(o4 * 4 + 3) * 128 + tid] = w1 * A.w + w2 * Bv.w;
    }
    __syncthreads();
    float* outp = out + (size_t)b * C_ * N_;
    for (int idx = tid; idx < C_ * 128; idx += 128) {
        int o = idx >> 7, il = idx & 127;
        outp[(size_t)o * N_ + i0 + il] = sout[idx];
    }
}

// ---------------- C_k handling ----------------
__global__ void k_flag_scan(const float* __restrict__ Ck) {
    const float4* f4 = (const float4*)Ck;
    const int total4 = (N_ * N_) / 4;            // 4,194,304
    int gid = blockIdx.x * blockDim.x + threadIdx.x;
    for (int v = gid; v < total4; v += gridDim.x * blockDim.x) {
        float4 c = f4[v];
        if (c.x != 0.f || c.y != 0.f || c.z != 0.f || c.w != 0.f) d_flag = 1;
    }
}

// cold path: y += C_k @ g_x  (only runs when C_k has any nonzero)
__global__ void k_ckgemm(const float* __restrict__ Ck, float* __restrict__ out) {
    if (!d_flag) return;
    __shared__ float Ash[64][65];
    __shared__ float Bsh[64][64];
    int t = threadIdx.x;          // 256
    int b = blockIdx.y;
    int i0 = blockIdx.x * 64;
    int ti = t >> 4, to = t & 15;
    float acc[4][4];
#pragma unroll
    for (int a = 0; a < 4; ++a)
#pragma unroll
        for (int c = 0; c < 4; ++c) acc[a][c] = 0.f;

    for (int j0 = 0; j0 < N_; j0 += 64) {
        for (int idx = t; idx < 4096; idx += 256) {
            int ii = idx >> 6, jj = idx & 63;
            Ash[ii][jj] = Ck[(size_t)(i0 + ii) * N_ + j0 + jj];
        }
        for (int idx = t; idx < 4096; idx += 256) {
            int jj = idx >> 6, o = idx & 63;
            Bsh[jj][o] = d_g[((size_t)b * N_ + j0 + jj) * C_ + o];
        }
        __syncthreads();
        for (int jj = 0; jj < 64; ++jj) {
            float a0 = Ash[ti * 4 + 0][jj], a1 = Ash[ti * 4 + 1][jj];
            float a2 = Ash[ti * 4 + 2][jj], a3 = Ash[ti * 4 + 3][jj];
            float b0 = Bsh[jj][to * 4 + 0], b1 = Bsh[jj][to * 4 + 1];
            float b2 = Bsh[jj][to * 4 + 2], b3 = Bsh[jj][to * 4 + 3];
            acc[0][0] += a0 * b0; acc[0][1] += a0 * b1; acc[0][2] += a0 * b2; acc[0][3] += a0 * b3;
            acc[1][0] += a1 * b0; acc[1][1] += a1 * b1; acc[1][2] += a1 * b2; acc[1][3] += a1 * b3;
            acc[2][0] += a2 * b0; acc[2][1] += a2 * b1; acc[2][2] += a2 * b2; acc[2][3] += a2 * b3;
            acc[3][0] += a3 * b0; acc[3][1] += a3 * b1; acc[3][2] += a3 * b2; acc[3][3] += a3 * b3;
        }
        __syncthreads();
    }
#pragma unroll
    for (int ii = 0; ii < 4; ++ii)
#pragma unroll
        for (int oo = 0; oo < 4; ++oo)
            out[((size_t)b * C_ + to * 4 + oo) * N_ + i0 + ti * 4 + ii] += acc[ii][oo];
}

// ---------------- launch ----------------
extern "C" void kernel_launch(void* const* d_in, const int* in_sizes, int n_in,
                              void* d_out, int out_size) {
    const float* x   = (const float*)d_in[0];
    const float* gw  = (const float*)d_in[1];
    const float* gb  = (const float*)d_in[2];
    const float* tw  = (const float*)d_in[3];
    const float* tb  = (const float*)d_in[4];
    const float* pw  = (const float*)d_in[5];
    const float* pb  = (const float*)d_in[6];
    const float* cp  = (const float*)d_in[7];
    const float* Ck  = (const float*)d_in[8];
    float* out = (float*)d_out;

    k_prep<<<1, 64>>>(tw, tb, pw, pb, cp);
    k_flag_scan<<<4096, 256>>>(Ck);
    k_gxap<<<dim3(32, B_), 256>>>(x, gw, gb);
    k_csort<<<dim3(4, B_), 512>>>();
    k_merge<1024><<<dim3(16, B_), 256>>>();
    k_merge<2048><<<dim3(16, B_), 256>>>();
    k_tscan<<<B_, 512>>>();
    k_scanA<<<dim3(64, B_), 512>>>();
    k_scanB<<<8, 1024>>>();
    k_scanC<<<dim3(64, B_), 512>>>();
    k_final<<<dim3(32, B_), 128>>>(out);
    k_ckgemm<<<dim3(64, B_), 256>>>(Ck, out);
}